// round 16
// baseline (speedup 1.0000x reference)
#include <cuda_runtime.h>
#include <cuda_bf16.h>
#include <cuda_fp16.h>
#include <math.h>
#include <cstdint>

#define EMBED   512
#define HEADS   8
#define HDIM    64
#define TT      6
#define NNODES  30000
#define NGRAPHS 512
#define M_ROWS  (NNODES * TT)   /* 180000 */
#define NCOLS   1024            /* 512 Q cols + 512 K cols */

#define RESID_SCALE    2048.0f          /* 2^11 */
#define RESID_INV      4.8828125e-4f    /* 2^-11 */

#define MTILES      2813                /* ceil(180000/64) */
#define NB_CTAS     256                 /* splitB CTAs */
#define NSA_CTAS    45000               /* splitA CTAs (4 rows each) */
#define NG_CTAS     (16 * MTILES)       /* 45008 GEMM CTAs */
#define INTER_CTAS  (2 * NSA_CTAS)      /* 90000 interleaved */
#define TOTAL_CTAS  (NB_CTAS + INTER_CTAS + (NG_CTAS - NSA_CTAS))  /* 90264 */

/* Scratch */
__device__ float g_qk[(size_t)M_ROWS * NCOLS];
__device__ __half g_As[2ull * M_ROWS * EMBED];   /* fp16 split planes of X  */
__device__ __half g_Bs[2ull * NCOLS * EMBED];    /* fp16 split planes of [Wq;Wk] */
__device__ int g_cntA[MTILES];
__device__ int g_cntB;

/* ================= helpers ================= */
__device__ __forceinline__ uint32_t smem_u32(const void* p) {
    uint32_t a;
    asm("{ .reg .u64 t; cvta.to.shared.u64 t, %1; cvt.u32.u64 %0, t; }" : "=r"(a) : "l"(p));
    return a;
}
__device__ __forceinline__ void cp16(uint32_t dst, const void* src, bool pred) {
    int sz = pred ? 16 : 0;
    asm volatile("cp.async.cg.shared.global [%0], [%1], 16, %2;"
                 :: "r"(dst), "l"(src), "r"(sz) : "memory");
}
__device__ __forceinline__ void ldsm_x4(uint32_t* r, uint32_t addr) {
    asm volatile("ldmatrix.sync.aligned.m8n8.x4.shared.b16 {%0,%1,%2,%3}, [%4];"
                 : "=r"(r[0]), "=r"(r[1]), "=r"(r[2]), "=r"(r[3]) : "r"(addr));
}
__device__ __forceinline__ void mma_f16(float* c, const uint32_t* a, const uint32_t* b) {
    asm volatile("mma.sync.aligned.m16n8k16.row.col.f32.f16.f16.f32 "
                 "{%0,%1,%2,%3}, {%4,%5,%6,%7}, {%8,%9}, {%0,%1,%2,%3};"
                 : "+f"(c[0]), "+f"(c[1]), "+f"(c[2]), "+f"(c[3])
                 : "r"(a[0]), "r"(a[1]), "r"(a[2]), "r"(a[3]), "r"(b[0]), "r"(b[1]));
}

/* ========== fp16x2 RN split with scaled residual plane ========== */
__device__ __forceinline__ void split2s(float x, __half& a0, __half& a1) {
    a0 = __float2half_rn(x);
    a1 = __float2half_rn((x - __half2float(a0)) * RESID_SCALE);
}
__device__ __forceinline__ void split_quad(float4 x, uint2& p0, uint2& p1) {
    __half a0, a1, b0, b1, c0, c1, d0, d1;
    split2s(x.x, a0, a1);
    split2s(x.y, b0, b1);
    split2s(x.z, c0, c1);
    split2s(x.w, d0, d1);
    __half2 h0 = __half2(a0, b0), h1 = __half2(c0, d0);
    __half2 h2 = __half2(a1, b1), h3 = __half2(c1, d1);
    p0.x = *(uint32_t*)&h0; p0.y = *(uint32_t*)&h1;
    p1.x = *(uint32_t*)&h2; p1.y = *(uint32_t*)&h3;
}

/* ================= counter zero kernel (runs first, each launch) ====== */
__global__ void zero_kernel() {
    int i = blockIdx.x * blockDim.x + threadIdx.x;
    if (i < MTILES) g_cntA[i] = 0;
    if (i == 0) g_cntB = 0;
}

/* ================= GEMM tile constants (R10 structure, unchanged) ===== */
#define BK          32
#define KCHUNKS     (EMBED / BK)        /* 16 */
#define A_TILE_B    (64 * 64)
#define B_TILE_B    (64 * 64)
#define STAGE_B     (2 * A_TILE_B + 2 * B_TILE_B)   /* 16 KB */
#define NSTAGE      3
#define SMEM_TOTAL  (NSTAGE * STAGE_B)              /* 48 KB */

__device__ __forceinline__ void load_chunk(uint32_t sb, int stage, int kc,
                                           int m0, int n0, int tid) {
    const size_t SPA = (size_t)M_ROWS * EMBED;
    const size_t SPB = (size_t)NCOLS * EMBED;
    uint32_t base = sb + stage * STAGE_B;
#pragma unroll
    for (int i = 0; i < 4; i++) {
        int o = tid + i * 128;
        int split = o >> 8;
        int rem = o & 255;
        int row = rem >> 2;
        int g = rem & 3;
        int gs = g ^ ((row >> 1) & 3);
        int m = m0 + row;
        bool v = (m < M_ROWS);
        const __half* src = g_As + split * SPA
                          + (size_t)(v ? m : 0) * EMBED + kc * BK + g * 8;
        cp16(base + split * A_TILE_B + row * 64 + gs * 16, src, v);
    }
#pragma unroll
    for (int i = 0; i < 4; i++) {
        int o = tid + i * 128;
        int split = o >> 8;
        int rem = o & 255;
        int row = rem >> 2;
        int g = rem & 3;
        int gs = g ^ ((row >> 1) & 3);
        const __half* src = g_Bs + split * SPB
                          + (size_t)(n0 + row) * EMBED + kc * BK + g * 8;
        cp16(base + 2 * A_TILE_B + split * B_TILE_B + row * 64 + gs * 16, src, true);
    }
    asm volatile("cp.async.commit_group;" ::: "memory");
}

/* ================= fused split + GEMM kernel ================= */
__global__ __launch_bounds__(128, 4)
void fused_kernel(const float* __restrict__ X,
                  const float* __restrict__ Wq, const float* __restrict__ Wk,
                  const float* __restrict__ bq, const float* __restrict__ bk) {
    const int bid = blockIdx.x;
    const int tid = threadIdx.x;

    /* ---------- role decode ---------- */
    if (bid < NB_CTAS) {
        /* splitB: 512 quads per CTA */
        const size_t SPQ = (size_t)NCOLS * EMBED / 4;
#pragma unroll
        for (int q = 0; q < 4; q++) {
            size_t p = (size_t)bid * 512 + q * 128 + tid;
            size_t i = p * 4;
            size_t j = i >> 9;
            size_t k = i & 511;
            const float* src = (j < 512) ? (Wq + j * 512 + k) : (Wk + (j - 512) * 512 + k);
            float4 x = *(const float4*)src;
            uint2 p0, p1;
            split_quad(x, p0, p1);
            ((uint2*)g_Bs)[p] = p0;
            ((uint2*)g_Bs)[SPQ + p] = p1;
        }
        __threadfence();
        __syncthreads();
        if (tid == 0) atomicAdd(&g_cntB, 1);
        return;
    }

    int r = bid - NB_CTAS;
    int gemm_idx = -1;
    if (r < INTER_CTAS) {
        int idx = r >> 1;
        if ((r & 1) == 0) {
            /* splitA CTA idx: quads [512*idx, 512*idx+512) = rows [4idx,4idx+4) */
            const size_t SPQ = (size_t)M_ROWS * EMBED / 4;
#pragma unroll
            for (int q = 0; q < 4; q++) {
                size_t p = (size_t)idx * 512 + q * 128 + tid;
                float4 x = ((const float4*)X)[p];
                uint2 p0, p1;
                split_quad(x, p0, p1);
                ((uint2*)g_As)[p] = p0;
                ((uint2*)g_As)[SPQ + p] = p1;
            }
            __threadfence();
            __syncthreads();
            if (tid == 0) atomicAdd(&g_cntA[idx >> 4], 1);
            return;
        }
        gemm_idx = idx;
    } else {
        gemm_idx = NSA_CTAS + (r - INTER_CTAS);
    }

    /* ---------- GEMM CTA ---------- */
    const int m_tile = gemm_idx >> 4;        /* 0..2812 */
    const int n_tile = gemm_idx & 15;
    const int m0 = m_tile * 64;
    const int n0 = n_tile * 64;

    /* wait for deps: this mtile's A split + all of B split */
    if (tid == 0) {
        int tgt = M_ROWS - m0;
        tgt = (tgt > 64 ? 64 : tgt) >> 2;    /* 16, or 8 for last tile */
        volatile int* ca = (volatile int*)&g_cntA[m_tile];
        volatile int* cb = (volatile int*)&g_cntB;
        while (*ca < tgt) __nanosleep(64);
        while (*cb < NB_CTAS) __nanosleep(64);
    }
    __syncthreads();
    __threadfence();

    extern __shared__ char smem[];
    uint32_t sb = smem_u32(smem);
    const int wid = tid >> 5;
    const int lane = tid & 31;
    const int warp_m = (wid >> 1) * 32;
    const int warp_n = (wid & 1) * 32;

    float c_main[2][4][4];
    float c_rest[2][4][4];
#pragma unroll
    for (int im = 0; im < 2; im++)
#pragma unroll
        for (int jn = 0; jn < 4; jn++)
#pragma unroll
            for (int q = 0; q < 4; q++) { c_main[im][jn][q] = 0.f; c_rest[im][jn][q] = 0.f; }

    load_chunk(sb, 0, 0, m0, n0, tid);
    load_chunk(sb, 1, 1, m0, n0, tid);

    const int a_r = (lane & 7) + ((lane >> 3) & 1) * 8;
    const int a_g = (lane >> 4) & 1;
    const int b_r = (lane & 7) + ((lane >> 4) & 1) * 8;
    const int b_g = (lane >> 3) & 1;

    for (int kc = 0; kc < KCHUNKS; kc++) {
        const int st = kc % NSTAGE;
        asm volatile("cp.async.wait_group 1;" ::: "memory");
        __syncthreads();

        if (kc + NSTAGE - 1 < KCHUNKS)
            load_chunk(sb, (kc + NSTAGE - 1) % NSTAGE, kc + NSTAGE - 1, m0, n0, tid);
        else
            asm volatile("cp.async.commit_group;" ::: "memory");

        const uint32_t abase = sb + st * STAGE_B;
        const uint32_t bbase = abase + 2 * A_TILE_B;

#pragma unroll
        for (int ks = 0; ks < 2; ks++) {
            uint32_t bf[2][2][4];
#pragma unroll
            for (int s = 0; s < 2; s++)
#pragma unroll
                for (int j2 = 0; j2 < 2; j2++) {
                    int row = warp_n + j2 * 16 + b_r;
                    int g = ks * 2 + b_g;
                    int gs = g ^ ((row >> 1) & 3);
                    ldsm_x4(bf[s][j2], bbase + s * B_TILE_B + row * 64 + gs * 16);
                }
            {
                uint32_t af[2][4];
#pragma unroll
                for (int im = 0; im < 2; im++) {
                    int row = warp_m + im * 16 + a_r;
                    int g = ks * 2 + a_g;
                    int gs = g ^ ((row >> 1) & 3);
                    ldsm_x4(af[im], abase + 0 * A_TILE_B + row * 64 + gs * 16);
                }
#pragma unroll
                for (int im = 0; im < 2; im++)
#pragma unroll
                    for (int jn = 0; jn < 4; jn++)
                        mma_f16(c_main[im][jn], af[im], &bf[0][jn >> 1][(jn & 1) * 2]);
#pragma unroll
                for (int im = 0; im < 2; im++)
#pragma unroll
                    for (int jn = 0; jn < 4; jn++)
                        mma_f16(c_rest[im][jn], af[im], &bf[1][jn >> 1][(jn & 1) * 2]);
            }
            {
                uint32_t af[2][4];
#pragma unroll
                for (int im = 0; im < 2; im++) {
                    int row = warp_m + im * 16 + a_r;
                    int g = ks * 2 + a_g;
                    int gs = g ^ ((row >> 1) & 3);
                    ldsm_x4(af[im], abase + 1 * A_TILE_B + row * 64 + gs * 16);
                }
#pragma unroll
                for (int im = 0; im < 2; im++)
#pragma unroll
                    for (int jn = 0; jn < 4; jn++)
                        mma_f16(c_rest[im][jn], af[im], &bf[0][jn >> 1][(jn & 1) * 2]);
            }
        }
    }

    /* epilogue: result = c_main + (c_rest * 2^-11 + bias) */
    const float* bias = (n0 < 512) ? (bq + n0) : (bk + (n0 - 512));
#pragma unroll
    for (int im = 0; im < 2; im++) {
#pragma unroll
        for (int jn = 0; jn < 4; jn++) {
            int col = warp_n + jn * 8 + (lane & 3) * 2;
            float b0 = bias[col], b1 = bias[col + 1];
            int row0 = m0 + warp_m + im * 16 + (lane >> 2);
            if (row0 < M_ROWS) {
                float2 v = make_float2(
                    c_main[im][jn][0] + fmaf(c_rest[im][jn][0], RESID_INV, b0),
                    c_main[im][jn][1] + fmaf(c_rest[im][jn][1], RESID_INV, b1));
                *(float2*)(g_qk + (size_t)row0 * NCOLS + n0 + col) = v;
            }
            int row1 = row0 + 8;
            if (row1 < M_ROWS) {
                float2 v = make_float2(
                    c_main[im][jn][2] + fmaf(c_rest[im][jn][2], RESID_INV, b0),
                    c_main[im][jn][3] + fmaf(c_rest[im][jn][3], RESID_INV, b1));
                *(float2*)(g_qk + (size_t)row1 * NCOLS + n0 + col) = v;
            }
        }
    }
}

/* ================= attention (R10 exact: V in regs, gate inlined) ===== */
#define EPAD (EMBED + 4)

__global__ __launch_bounds__(128)
void attn_kernel(const float* __restrict__ emb,
                 const float* __restrict__ ac,
                 const float* __restrict__ Wg,
                 const float* __restrict__ bg,
                 const int* __restrict__ batch,
                 float* __restrict__ out_ctx,
                 float* __restrict__ out_attn) {
    __shared__ float Qs[TT][EPAD];
    __shared__ float Ks[TT][EPAD];
    __shared__ float Ssc[HEADS][TT][TT];
    __shared__ float Sat[HEADS][TT][TT];
    __shared__ float Sg[TT];

    const int node = blockIdx.x;
    const int tid = threadIdx.x;

    const float4* qkb = (const float4*)(g_qk + (size_t)node * TT * NCOLS);
    const float4* vb  = (const float4*)(emb + (size_t)node * TT * EMBED);

    float4 vreg[TT];
#pragma unroll
    for (int s = 0; s < TT; s++) vreg[s] = vb[s * 128 + tid];

#pragma unroll
    for (int t = 0; t < TT; t++) {
        float4 q = qkb[t * 256 + tid];
        float4 k = qkb[t * 256 + 128 + tid];
        ((float4*)Qs[t])[tid] = q;
        ((float4*)Ks[t])[tid] = k;
    }
    if (tid < TT) {
        int g = batch[node];
        float acc = bg[tid];
#pragma unroll
        for (int j = 0; j < 5; j++) acc += ac[g * 5 + j] * Wg[tid * 5 + j];
        Sg[tid] = acc;
    }
    __syncthreads();

    for (int task = tid; task < HEADS * TT * TT; task += 128) {
        int h = task / 36;
        int r = task % 36;
        int t = r / 6, s = r % 6;
        const float4* qp = (const float4*)&Qs[t][h * HDIM];
        const float4* kp = (const float4*)&Ks[s][h * HDIM];
        float a0 = 0.f;
#pragma unroll
        for (int d = 0; d < 16; d++) {
            float4 a = qp[d], b = kp[d];
            a0 += a.x * b.x + a.y * b.y + a.z * b.z + a.w * b.w;
        }
        Ssc[h][t][s] = a0 * 0.125f * Sg[s];
    }
    __syncthreads();

    if (tid < HEADS * TT) {
        int h = tid / 6, t = tid % 6;
        float sc[6], ab[6];
#pragma unroll
        for (int s = 0; s < 6; s++) {
            sc[s] = Ssc[h][t][s];
            ab[s] = fabsf(sc[s]);
        }
        bool keep[6];
        float mx = -INFINITY;
#pragma unroll
        for (int i = 0; i < 6; i++) {
            int rank = 0;
#pragma unroll
            for (int j = 0; j < 6; j++)
                rank += (ab[j] > ab[i]) || (ab[j] == ab[i] && j < i);
            keep[i] = (rank < 4);
            if (keep[i]) mx = fmaxf(mx, sc[i]);
        }
        float e[6], sum = 0.f;
#pragma unroll
        for (int i = 0; i < 6; i++) {
            e[i] = keep[i] ? expf(sc[i] - mx) : 0.f;
            sum += e[i];
        }
        float inv = 1.0f / sum;
        float* oat = out_attn + (size_t)node * (HEADS * TT * TT) + tid * 6;
#pragma unroll
        for (int i = 0; i < 6; i++) {
            float a = e[i] * inv;
            Sat[h][t][i] = a;
            oat[i] = a;
        }
    }
    __syncthreads();

    float4* octx = (float4*)(out_ctx + (size_t)node * TT * EMBED);
    const int h = tid >> 4;
#pragma unroll
    for (int t = 0; t < TT; t++) {
        float4 a4 = make_float4(0.f, 0.f, 0.f, 0.f);
#pragma unroll
        for (int s = 0; s < 6; s++) {
            float a = Sat[h][t][s];
            float4 v = vreg[s];
            a4.x += a * v.x; a4.y += a * v.y;
            a4.z += a * v.z; a4.w += a * v.w;
        }
        octx[t * 128 + tid] = a4;
    }
}

/* ================= launch ================= */
extern "C" void kernel_launch(void* const* d_in, const int* in_sizes, int n_in,
                              void* d_out, int out_size) {
    const float* emb   = (const float*)d_in[0];
    const float* ac    = (const float*)d_in[1];
    const float* Wk    = (const float*)d_in[2];
    const float* bk    = (const float*)d_in[3];
    const float* Wq    = (const float*)d_in[4];
    const float* bq    = (const float*)d_in[5];
    const float* Wg    = (const float*)d_in[6];
    const float* bg    = (const float*)d_in[7];
    const int*   batch = (const int*)d_in[8];

    float* out = (float*)d_out;
    float* out_ctx  = out;
    float* out_attn = out + (size_t)NNODES * TT * EMBED;

    zero_kernel<<<(MTILES + 255) / 256, 256>>>();

    cudaFuncSetAttribute(fused_kernel, cudaFuncAttributeMaxDynamicSharedMemorySize, SMEM_TOTAL);
    fused_kernel<<<TOTAL_CTAS, 128, SMEM_TOTAL>>>(emb, Wq, Wk, bq, bk);

    attn_kernel<<<NNODES, 128>>>(emb, ac, Wg, bg, batch, out_ctx, out_attn);
}

// round 17
// speedup vs baseline: 1.0651x; 1.0651x over previous
#include <cuda_runtime.h>
#include <cuda_bf16.h>
#include <cuda_fp16.h>
#include <math.h>
#include <cstdint>

#define EMBED   512
#define HEADS   8
#define HDIM    64
#define TT      6
#define NNODES  30000
#define NGRAPHS 512
#define M_ROWS  (NNODES * TT)   /* 180000 */
#define NCOLS   1024            /* 512 Q cols + 512 K cols */

#define RESID_SCALE    2048.0f          /* 2^11 */
#define RESID_INV      4.8828125e-4f    /* 2^-11 */

/* Scratch */
__device__ float g_qk[(size_t)M_ROWS * NCOLS];
__device__ __half g_As[2ull * M_ROWS * EMBED];   /* fp16 split planes of X  */
__device__ __half g_Bs[2ull * NCOLS * EMBED];    /* fp16 split planes of [Wq;Wk] */

/* ================= helpers ================= */
__device__ __forceinline__ uint32_t smem_u32(const void* p) {
    uint32_t a;
    asm("{ .reg .u64 t; cvta.to.shared.u64 t, %1; cvt.u32.u64 %0, t; }" : "=r"(a) : "l"(p));
    return a;
}
__device__ __forceinline__ void cp16(uint32_t dst, const void* src, bool pred) {
    int sz = pred ? 16 : 0;
    asm volatile("cp.async.cg.shared.global [%0], [%1], 16, %2;"
                 :: "r"(dst), "l"(src), "r"(sz) : "memory");
}
__device__ __forceinline__ void ldsm_x4(uint32_t* r, uint32_t addr) {
    asm volatile("ldmatrix.sync.aligned.m8n8.x4.shared.b16 {%0,%1,%2,%3}, [%4];"
                 : "=r"(r[0]), "=r"(r[1]), "=r"(r[2]), "=r"(r[3]) : "r"(addr));
}
__device__ __forceinline__ void mma_f16(float* c, const uint32_t* a, const uint32_t* b) {
    asm volatile("mma.sync.aligned.m16n8k16.row.col.f32.f16.f16.f32 "
                 "{%0,%1,%2,%3}, {%4,%5,%6,%7}, {%8,%9}, {%0,%1,%2,%3};"
                 : "+f"(c[0]), "+f"(c[1]), "+f"(c[2]), "+f"(c[3])
                 : "r"(a[0]), "r"(a[1]), "r"(a[2]), "r"(a[3]), "r"(b[0]), "r"(b[1]));
}

/* ========== fp16x2 RN split with scaled residual plane ==========
 * a0 = RN16(x);  a1' = RN16(2^11 * (x - a0))  (normal-range, no subnormals) */
__device__ __forceinline__ void split2s(float x, __half& a0, __half& a1) {
    a0 = __float2half_rn(x);
    a1 = __float2half_rn((x - __half2float(a0)) * RESID_SCALE);
}
__device__ __forceinline__ void split_quad(float4 x, uint2& p0, uint2& p1) {
    __half a0, a1, b0, b1, c0, c1, d0, d1;
    split2s(x.x, a0, a1);
    split2s(x.y, b0, b1);
    split2s(x.z, c0, c1);
    split2s(x.w, d0, d1);
    __half2 h0 = __half2(a0, b0), h1 = __half2(c0, d0);
    __half2 h2 = __half2(a1, b1), h3 = __half2(c1, d1);
    p0.x = *(uint32_t*)&h0; p0.y = *(uint32_t*)&h1;
    p1.x = *(uint32_t*)&h2; p1.y = *(uint32_t*)&h3;
}

/* ======= split kernel: 512 quads per block, 2 per thread (ILP) =======
 * A_QUADS and B_QUADS are both divisible by 512 -> homogeneous blocks.  */
#define A_QUADS ((size_t)M_ROWS * EMBED / 4)   /* 23,040,000 */
#define B_QUADS ((size_t)NCOLS * EMBED / 4)    /* 131,072 */
#define A_BLOCKS (A_QUADS / 512)               /* 45,000 */
#define B_BLOCKS (B_QUADS / 512)               /* 256 */

__global__ void split_kernel(const float* __restrict__ X,
                             const float* __restrict__ Wq,
                             const float* __restrict__ Wk) {
    const int tid = threadIdx.x;
    const size_t bb = (size_t)blockIdx.x;
    if (bb < A_BLOCKS) {
        const size_t SPQ = A_QUADS;            /* quads per plane */
        size_t g0 = bb * 512 + tid;
        size_t g1 = g0 + 256;
        /* two independent load->convert->store chains for MLP */
        float4 x0 = ((const float4*)X)[g0];
        float4 x1 = ((const float4*)X)[g1];
        uint2 a0, a1, b0, b1;
        split_quad(x0, a0, a1);
        split_quad(x1, b0, b1);
        ((uint2*)g_As)[g0] = a0;
        ((uint2*)g_As)[g1] = b0;
        ((uint2*)g_As)[SPQ + g0] = a1;
        ((uint2*)g_As)[SPQ + g1] = b1;
    } else {
        const size_t SPQ = B_QUADS;
        size_t p0 = (bb - A_BLOCKS) * 512 + tid;
#pragma unroll
        for (int u = 0; u < 2; u++) {
            size_t p = p0 + u * 256;
            size_t i = p * 4;
            size_t j = i >> 9;
            size_t k = i & 511;
            const float* src = (j < 512) ? (Wq + j * 512 + k) : (Wk + (j - 512) * 512 + k);
            float4 x = *(const float4*)src;
            uint2 q0, q1;
            split_quad(x, q0, q1);
            ((uint2*)g_Bs)[p] = q0;
            ((uint2*)g_Bs)[SPQ + p] = q1;
        }
    }
}

/* ================= mma.sync fp16x2 GEMM, 3 products, dual-class =====
 * c_main: a0*b0.   c_rest: a0*b1' + a1'*b0   (both carry 2^11 factor).
 * result = c_main + (c_rest * 2^-11 + bias).
 * BM=64, BN=64, BK=32. 128 threads (4 warps, 2x2 warp grid, tile 32x32).
 * 3-stage cp.async pipeline, 4 CTAs/SM.  (R10 structure - best known)   */
#define BK          32
#define KCHUNKS     (EMBED / BK)        /* 16 */
#define A_TILE_B    (64 * 64)           /* per split: 64 rows x 64 B */
#define B_TILE_B    (64 * 64)
#define STAGE_B     (2 * A_TILE_B + 2 * B_TILE_B)   /* 16 KB */
#define NSTAGE      3
#define SMEM_TOTAL  (NSTAGE * STAGE_B)              /* 48 KB */

__device__ __forceinline__ void load_chunk(uint32_t sb, int stage, int kc,
                                           int m0, int n0, int tid) {
    const size_t SPA = (size_t)M_ROWS * EMBED;
    const size_t SPB = (size_t)NCOLS * EMBED;
    uint32_t base = sb + stage * STAGE_B;
#pragma unroll
    for (int i = 0; i < 4; i++) {
        int o = tid + i * 128;
        int split = o >> 8;
        int rem = o & 255;
        int row = rem >> 2;
        int g = rem & 3;
        int gs = g ^ ((row >> 1) & 3);
        int m = m0 + row;
        bool v = (m < M_ROWS);
        const __half* src = g_As + split * SPA
                          + (size_t)(v ? m : 0) * EMBED + kc * BK + g * 8;
        cp16(base + split * A_TILE_B + row * 64 + gs * 16, src, v);
    }
#pragma unroll
    for (int i = 0; i < 4; i++) {
        int o = tid + i * 128;
        int split = o >> 8;
        int rem = o & 255;
        int row = rem >> 2;
        int g = rem & 3;
        int gs = g ^ ((row >> 1) & 3);
        const __half* src = g_Bs + split * SPB
                          + (size_t)(n0 + row) * EMBED + kc * BK + g * 8;
        cp16(base + 2 * A_TILE_B + split * B_TILE_B + row * 64 + gs * 16, src, true);
    }
    asm volatile("cp.async.commit_group;" ::: "memory");
}

__global__ __launch_bounds__(128, 4)
void qk_gemm_mma(const float* __restrict__ bq, const float* __restrict__ bk) {
    extern __shared__ char smem[];
    uint32_t sb = smem_u32(smem);
    const int tid = threadIdx.x;
    const int wid = tid >> 5;
    const int lane = tid & 31;
    const int m0 = blockIdx.y * 64;
    const int n0 = blockIdx.x * 64;
    const int warp_m = (wid >> 1) * 32;
    const int warp_n = (wid & 1) * 32;

    float c_main[2][4][4];
    float c_rest[2][4][4];
#pragma unroll
    for (int im = 0; im < 2; im++)
#pragma unroll
        for (int jn = 0; jn < 4; jn++)
#pragma unroll
            for (int q = 0; q < 4; q++) { c_main[im][jn][q] = 0.f; c_rest[im][jn][q] = 0.f; }

    load_chunk(sb, 0, 0, m0, n0, tid);
    load_chunk(sb, 1, 1, m0, n0, tid);

    const int a_r = (lane & 7) + ((lane >> 3) & 1) * 8;
    const int a_g = (lane >> 4) & 1;
    const int b_r = (lane & 7) + ((lane >> 4) & 1) * 8;
    const int b_g = (lane >> 3) & 1;

    for (int kc = 0; kc < KCHUNKS; kc++) {
        const int st = kc % NSTAGE;
        asm volatile("cp.async.wait_group 1;" ::: "memory");
        __syncthreads();

        if (kc + NSTAGE - 1 < KCHUNKS)
            load_chunk(sb, (kc + NSTAGE - 1) % NSTAGE, kc + NSTAGE - 1, m0, n0, tid);
        else
            asm volatile("cp.async.commit_group;" ::: "memory");

        const uint32_t abase = sb + st * STAGE_B;
        const uint32_t bbase = abase + 2 * A_TILE_B;

#pragma unroll
        for (int ks = 0; ks < 2; ks++) {
            uint32_t bf[2][2][4];
#pragma unroll
            for (int s = 0; s < 2; s++)
#pragma unroll
                for (int j2 = 0; j2 < 2; j2++) {
                    int row = warp_n + j2 * 16 + b_r;
                    int g = ks * 2 + b_g;
                    int gs = g ^ ((row >> 1) & 3);
                    ldsm_x4(bf[s][j2], bbase + s * B_TILE_B + row * 64 + gs * 16);
                }
            {
                uint32_t af[2][4];
#pragma unroll
                for (int im = 0; im < 2; im++) {
                    int row = warp_m + im * 16 + a_r;
                    int g = ks * 2 + a_g;
                    int gs = g ^ ((row >> 1) & 3);
                    ldsm_x4(af[im], abase + 0 * A_TILE_B + row * 64 + gs * 16);
                }
#pragma unroll
                for (int im = 0; im < 2; im++)
#pragma unroll
                    for (int jn = 0; jn < 4; jn++)
                        mma_f16(c_main[im][jn], af[im], &bf[0][jn >> 1][(jn & 1) * 2]);
#pragma unroll
                for (int im = 0; im < 2; im++)
#pragma unroll
                    for (int jn = 0; jn < 4; jn++)
                        mma_f16(c_rest[im][jn], af[im], &bf[1][jn >> 1][(jn & 1) * 2]);
            }
            {
                uint32_t af[2][4];
#pragma unroll
                for (int im = 0; im < 2; im++) {
                    int row = warp_m + im * 16 + a_r;
                    int g = ks * 2 + a_g;
                    int gs = g ^ ((row >> 1) & 3);
                    ldsm_x4(af[im], abase + 1 * A_TILE_B + row * 64 + gs * 16);
                }
#pragma unroll
                for (int im = 0; im < 2; im++)
#pragma unroll
                    for (int jn = 0; jn < 4; jn++)
                        mma_f16(c_rest[im][jn], af[im], &bf[0][jn >> 1][(jn & 1) * 2]);
            }
        }
    }

    /* epilogue: result = c_main + (c_rest * 2^-11 + bias) */
    const float* bias = (n0 < 512) ? (bq + n0) : (bk + (n0 - 512));
#pragma unroll
    for (int im = 0; im < 2; im++) {
#pragma unroll
        for (int jn = 0; jn < 4; jn++) {
            int col = warp_n + jn * 8 + (lane & 3) * 2;
            float b0 = bias[col], b1 = bias[col + 1];
            int row0 = m0 + warp_m + im * 16 + (lane >> 2);
            if (row0 < M_ROWS) {
                float2 v = make_float2(
                    c_main[im][jn][0] + fmaf(c_rest[im][jn][0], RESID_INV, b0),
                    c_main[im][jn][1] + fmaf(c_rest[im][jn][1], RESID_INV, b1));
                *(float2*)(g_qk + (size_t)row0 * NCOLS + n0 + col) = v;
            }
            int row1 = row0 + 8;
            if (row1 < M_ROWS) {
                float2 v = make_float2(
                    c_main[im][jn][2] + fmaf(c_rest[im][jn][2], RESID_INV, b0),
                    c_main[im][jn][3] + fmaf(c_rest[im][jn][3], RESID_INV, b1));
                *(float2*)(g_qk + (size_t)row1 * NCOLS + n0 + col) = v;
            }
        }
    }
}

/* ================= attention (V in registers, gate inlined) ========== */
#define EPAD (EMBED + 4)

__global__ __launch_bounds__(128)
void attn_kernel(const float* __restrict__ emb,
                 const float* __restrict__ ac,
                 const float* __restrict__ Wg,
                 const float* __restrict__ bg,
                 const int* __restrict__ batch,
                 float* __restrict__ out_ctx,
                 float* __restrict__ out_attn) {
    __shared__ float Qs[TT][EPAD];
    __shared__ float Ks[TT][EPAD];
    __shared__ float Ssc[HEADS][TT][TT];
    __shared__ float Sat[HEADS][TT][TT];
    __shared__ float Sg[TT];

    const int node = blockIdx.x;
    const int tid = threadIdx.x;

    const float4* qkb = (const float4*)(g_qk + (size_t)node * TT * NCOLS);
    const float4* vb  = (const float4*)(emb + (size_t)node * TT * EMBED);

    float4 vreg[TT];
#pragma unroll
    for (int s = 0; s < TT; s++) vreg[s] = vb[s * 128 + tid];

#pragma unroll
    for (int t = 0; t < TT; t++) {
        float4 q = qkb[t * 256 + tid];
        float4 k = qkb[t * 256 + 128 + tid];
        ((float4*)Qs[t])[tid] = q;
        ((float4*)Ks[t])[tid] = k;
    }
    if (tid < TT) {
        int g = batch[node];
        float acc = bg[tid];
#pragma unroll
        for (int j = 0; j < 5; j++) acc += ac[g * 5 + j] * Wg[tid * 5 + j];
        Sg[tid] = acc;
    }
    __syncthreads();

    for (int task = tid; task < HEADS * TT * TT; task += 128) {
        int h = task / 36;
        int r = task % 36;
        int t = r / 6, s = r % 6;
        const float4* qp = (const float4*)&Qs[t][h * HDIM];
        const float4* kp = (const float4*)&Ks[s][h * HDIM];
        float a0 = 0.f;
#pragma unroll
        for (int d = 0; d < 16; d++) {
            float4 a = qp[d], b = kp[d];
            a0 += a.x * b.x + a.y * b.y + a.z * b.z + a.w * b.w;
        }
        Ssc[h][t][s] = a0 * 0.125f * Sg[s];
    }
    __syncthreads();

    if (tid < HEADS * TT) {
        int h = tid / 6, t = tid % 6;
        float sc[6], ab[6];
#pragma unroll
        for (int s = 0; s < 6; s++) {
            sc[s] = Ssc[h][t][s];
            ab[s] = fabsf(sc[s]);
        }
        bool keep[6];
        float mx = -INFINITY;
#pragma unroll
        for (int i = 0; i < 6; i++) {
            int rank = 0;
#pragma unroll
            for (int j = 0; j < 6; j++)
                rank += (ab[j] > ab[i]) || (ab[j] == ab[i] && j < i);
            keep[i] = (rank < 4);
            if (keep[i]) mx = fmaxf(mx, sc[i]);
        }
        float e[6], sum = 0.f;
#pragma unroll
        for (int i = 0; i < 6; i++) {
            e[i] = keep[i] ? expf(sc[i] - mx) : 0.f;
            sum += e[i];
        }
        float inv = 1.0f / sum;
        float* oat = out_attn + (size_t)node * (HEADS * TT * TT) + tid * 6;
#pragma unroll
        for (int i = 0; i < 6; i++) {
            float a = e[i] * inv;
            Sat[h][t][i] = a;
            oat[i] = a;
        }
    }
    __syncthreads();

    float4* octx = (float4*)(out_ctx + (size_t)node * TT * EMBED);
    const int h = tid >> 4;
#pragma unroll
    for (int t = 0; t < TT; t++) {
        float4 a4 = make_float4(0.f, 0.f, 0.f, 0.f);
#pragma unroll
        for (int s = 0; s < 6; s++) {
            float a = Sat[h][t][s];
            float4 v = vreg[s];
            a4.x += a * v.x; a4.y += a * v.y;
            a4.z += a * v.z; a4.w += a * v.w;
        }
        octx[t * 128 + tid] = a4;
    }
}

/* ================= launch ================= */
extern "C" void kernel_launch(void* const* d_in, const int* in_sizes, int n_in,
                              void* d_out, int out_size) {
    const float* emb   = (const float*)d_in[0];
    const float* ac    = (const float*)d_in[1];
    const float* Wk    = (const float*)d_in[2];
    const float* bk    = (const float*)d_in[3];
    const float* Wq    = (const float*)d_in[4];
    const float* bq    = (const float*)d_in[5];
    const float* Wg    = (const float*)d_in[6];
    const float* bg    = (const float*)d_in[7];
    const int*   batch = (const int*)d_in[8];

    float* out = (float*)d_out;
    float* out_ctx  = out;
    float* out_attn = out + (size_t)NNODES * TT * EMBED;

    split_kernel<<<(unsigned)(A_BLOCKS + B_BLOCKS), 256>>>(emb, Wq, Wk);

    cudaFuncSetAttribute(qk_gemm_mma, cudaFuncAttributeMaxDynamicSharedMemorySize, SMEM_TOTAL);
    qk_gemm_mma<<<dim3(NCOLS / 64, (M_ROWS + 63) / 64), 128, SMEM_TOTAL>>>(bq, bk);

    attn_kernel<<<NNODES, 128>>>(emb, ac, Wg, bg, batch, out_ctx, out_attn);
}